// round 16
// baseline (speedup 1.0000x reference)
#include <cuda_runtime.h>
#include <cuda_bf16.h>
#include <math.h>
#include <stdint.h>

#define Bb 2
#define Ss 2048
#define Dd 2048
#define Hh 16
#define HDd 128
#define BSr (Bb*Ss)
#define Kd 2048                     // physical K for projections
#define KQ3 (3*HDd)                 // 384
#define NT 32
#define NTRI 528
#define OUT_ELEMS (Bb*Ss*Dd)
#define QSCALE 0.08838834764831843f

// ---------------- scratch (device globals; referenced only from device code) ----
__device__ float g_v[Bb*Hh*Ss*HDd];
__device__ float g_ctx[Bb*Ss*Dd];
__device__ float g_lse[Bb*Hh*Ss];
__device__ float g_kpm_add[BSr];
__device__ float g_sc[(size_t)Bb*NTRI*Hh*4096];       // biased scores, lower-tri tiles
__device__ __nv_bfloat16 g_qs[(size_t)Bb*Hh*Ss*KQ3];  // q split [h|h|l], pre-scaled
__device__ __nv_bfloat16 g_ks[(size_t)Bb*Hh*Ss*KQ3];  // k split [h|l|h]
__device__ __nv_bfloat16 g_vt[(size_t)Bb*Hh*HDd*3*Ss];// V^T split [bh][d][h|l|h over s]
// h/l component arrays (K = 2048 physical)
__device__ __nv_bfloat16 g_xh[(size_t)BSr*Dd];
__device__ __nv_bfloat16 g_xl[(size_t)BSr*Dd];
__device__ __nv_bfloat16 g_wih[(size_t)3*Dd*Dd];
__device__ __nv_bfloat16 g_wil[(size_t)3*Dd*Dd];
__device__ __nv_bfloat16 g_woh[(size_t)Dd*Dd];
__device__ __nv_bfloat16 g_wol[(size_t)Dd*Dd];
__device__ __nv_bfloat16 g_cth[(size_t)BSr*Dd];
__device__ __nv_bfloat16 g_ctl[(size_t)BSr*Dd];

__device__ __forceinline__ void mma16816(float* c, const uint32_t* a, const uint32_t* b) {
    asm volatile("mma.sync.aligned.m16n8k16.row.col.f32.bf16.bf16.f32 "
        "{%0,%1,%2,%3}, {%4,%5,%6,%7}, {%8,%9}, {%0,%1,%2,%3};"
        : "+f"(c[0]), "+f"(c[1]), "+f"(c[2]), "+f"(c[3])
        : "r"(a[0]), "r"(a[1]), "r"(a[2]), "r"(a[3]), "r"(b[0]), "r"(b[1]));
}
__device__ __forceinline__ void ldsm4(uint32_t* r, uint32_t saddr) {
    asm volatile("ldmatrix.sync.aligned.m8n8.x4.shared.b16 {%0,%1,%2,%3}, [%4];"
        : "=r"(r[0]), "=r"(r[1]), "=r"(r[2]), "=r"(r[3]) : "r"(saddr));
}
__device__ __forceinline__ uint32_t pack_bf2(float x, float y) {
    __nv_bfloat162 p = __floats2bfloat162_rn(x, y);
    return *(uint32_t*)&p;
}
__device__ __forceinline__ uint32_t smem_u32(const void* p) {
    uint32_t a;
    asm("{ .reg .u64 t; cvta.to.shared.u64 t, %1; cvt.u32.u64 %0, t; }" : "=r"(a) : "l"(p));
    return a;
}

// ---------------- key_padding_mask normalizer ----------------
__global__ void mask_norm_kernel(const void* kpm, int n)
{
    __shared__ int s_mode;
    __shared__ int c_upper, c_lower, c_fbad;
    const unsigned char* bp = (const unsigned char*)kpm;
    const float* fp = (const float*)kpm;
    int tid = threadIdx.x;
    if (tid == 0) { c_upper = 0; c_lower = 0; c_fbad = 0; }
    __syncthreads();
    for (int i = tid; i < n; i += blockDim.x) {
        unsigned char v = bp[i];
        if (v) { if (i & 3) atomicAdd(&c_upper, 1); else atomicAdd(&c_lower, 1); }
    }
    for (int i = tid; i < n / 4; i += blockDim.x) {
        float v = fp[i];
        if (!(v == 0.0f || v == 1.0f)) atomicAdd(&c_fbad, 1);
    }
    __syncthreads();
    if (tid == 0) {
        if (c_upper == 0 && c_lower == 0) s_mode = 2;
        else if (c_fbad == 0) s_mode = 0;
        else if (c_upper == 0) s_mode = 1;
        else s_mode = 2;
    }
    __syncthreads();
    int mode = s_mode;
    for (int i = tid; i < n; i += blockDim.x) {
        bool keep;
        if (mode == 0)      keep = (fp[i] != 0.0f);
        else if (mode == 1) keep = (((const int*)kpm)[i] != 0);
        else                keep = (bp[i] != 0);
        g_kpm_add[i] = keep ? 0.0f : -1e30f;
    }
}

// ---------------- fp32 -> bf16 h/l component split ----------------
// dsel: 0=(g_xh,g_xl) 1=(g_wih,g_wil) 2=(g_woh,g_wol) 3=(g_cth,g_ctl); src==nullptr -> g_ctx
__global__ void split_kernel(const float* __restrict__ src, long long n4, int dsel)
{
    long long i = (long long)blockIdx.x * blockDim.x + threadIdx.x;
    if (i >= n4) return;
    if (src == nullptr) src = g_ctx;
    __nv_bfloat16* dh = (dsel == 0) ? g_xh : (dsel == 1) ? g_wih
                      : (dsel == 2) ? g_woh : g_cth;
    __nv_bfloat16* dl = (dsel == 0) ? g_xl : (dsel == 1) ? g_wil
                      : (dsel == 2) ? g_wol : g_ctl;
    long long e = i * 4;
    float4 v = *(const float4*)(src + e);
    float f[4] = {v.x, v.y, v.z, v.w};
    __nv_bfloat16 h[4], l[4];
    #pragma unroll
    for (int j = 0; j < 4; j++) {
        h[j] = __float2bfloat16(f[j]);
        l[j] = __float2bfloat16(f[j] - __bfloat162float(h[j]));
    }
    uint32_t hp0 = ((uint32_t)__bfloat16_as_ushort(h[1]) << 16) | __bfloat16_as_ushort(h[0]);
    uint32_t hp1 = ((uint32_t)__bfloat16_as_ushort(h[3]) << 16) | __bfloat16_as_ushort(h[2]);
    uint32_t lp0 = ((uint32_t)__bfloat16_as_ushort(l[1]) << 16) | __bfloat16_as_ushort(l[0]);
    uint32_t lp1 = ((uint32_t)__bfloat16_as_ushort(l[3]) << 16) | __bfloat16_as_ushort(l[2]);
    *(uint2*)(dh + e) = make_uint2(hp0, hp1);
    *(uint2*)(dl + e) = make_uint2(lp0, lp1);
}

// ---------------- bf16 mma.sync NT GEMM, h/l component form ----------------
// C = Ah*Bh^T + Ah*Bl^T + Al*Bh^T over physical K=2048.
// 32-k chunks, 2-stage smem (1 sync/chunk), ldmatrix fragments.
#define LDWc 20                       // words per row (16 data + 4 pad)
#define CSTG (128*LDWc)               // words per component tile (2560)
#define STGW (4*CSTG)                 // words per stage {Ah,Al,Bh,Bl} = 10240
#define GM_SMEM (2*STGW*4)            // 81920 bytes

__global__ __launch_bounds__(256)
void gemm_mma_kernel(int absel, const float* __restrict__ bias, float* __restrict__ Cout,
                     int N, int epi)
{
    extern __shared__ uint32_t gsm[];

    const __nv_bfloat16* AH = (absel == 0) ? g_xh  : g_cth;
    const __nv_bfloat16* AL = (absel == 0) ? g_xl  : g_ctl;
    const __nv_bfloat16* BH = (absel == 0) ? g_wih : g_woh;
    const __nv_bfloat16* BL = (absel == 0) ? g_wil : g_wol;

    const int tid = threadIdx.x;
    const int m0 = blockIdx.y * 128, n0 = blockIdx.x * 128;
    const int NCH = Kd / 32;           // 64 chunks
    const int wstride = Kd / 2;        // 1024 words per global row

    const uint32_t* ahw = (const uint32_t*)(AH + (size_t)m0 * Kd);
    const uint32_t* alw = (const uint32_t*)(AL + (size_t)m0 * Kd);
    const uint32_t* bhw = (const uint32_t*)(BH + (size_t)n0 * Kd);
    const uint32_t* blw = (const uint32_t*)(BL + (size_t)n0 * Kd);

    // loader: 256 threads, 2 threads/row; each thread 2 uint4 per component
    const int lrow = tid >> 1;
    const int lu8  = (tid & 1) * 8;    // word offset 0 or 8 within 16-word chunk row
    const int w = tid >> 5, l = tid & 31;
    const int wm = (w >> 2) * 64, wn = (w & 3) * 32;
    const int g = l >> 2, t = l & 3;

    // ldmatrix lane base addresses (stage 0, bytes)
    const uint32_t sbase = smem_u32(gsm);
    const uint32_t aOff = ((((wm + (l & 15)) * LDWc) + ((l >> 4) << 2)) << 2);
    const uint32_t bOff = ((((wn + ((l >> 4) << 3) + (l & 7)) * LDWc) + (((l >> 3) & 1) << 2)) << 2);
    const uint32_t AHb = sbase + aOff;
    const uint32_t ALb = sbase + (CSTG << 2) + aOff;
    const uint32_t BHb = sbase + (2 * CSTG << 2) + bOff;
    const uint32_t BLb = sbase + (3 * CSTG << 2) + bOff;

    float acc[4][4][4];
    #pragma unroll
    for (int i = 0; i < 4; i++)
        #pragma unroll
        for (int j = 0; j < 4; j++)
            #pragma unroll
            for (int q = 0; q < 4; q++) acc[i][j][q] = 0.0f;

    uint4 rah[2], ral[2], rbh[2], rbl[2];
    #pragma unroll
    for (int i = 0; i < 2; i++) {
        size_t go = (size_t)lrow * wstride + lu8 + i * 4;
        rah[i] = *(const uint4*)&ahw[go];
        ral[i] = *(const uint4*)&alw[go];
        rbh[i] = *(const uint4*)&bhw[go];
        rbl[i] = *(const uint4*)&blw[go];
    }

    for (int c = 0; c < NCH; c++) {
        const int s = c & 1;
        uint32_t* st = gsm + s * STGW;
        const int so = lrow * LDWc + lu8;
        #pragma unroll
        for (int i = 0; i < 2; i++) {
            *(uint4*)&st[so + i * 4]            = rah[i];
            *(uint4*)&st[CSTG + so + i * 4]     = ral[i];
            *(uint4*)&st[2*CSTG + so + i * 4]   = rbh[i];
            *(uint4*)&st[3*CSTG + so + i * 4]   = rbl[i];
        }
        __syncthreads();
        if (c + 1 < NCH) {
            const int cw = (c + 1) * 16;
            #pragma unroll
            for (int i = 0; i < 2; i++) {
                size_t go = (size_t)lrow * wstride + cw + lu8 + i * 4;
                rah[i] = *(const uint4*)&ahw[go];
                ral[i] = *(const uint4*)&alw[go];
                rbh[i] = *(const uint4*)&bhw[go];
                rbl[i] = *(const uint4*)&blw[go];
            }
        }
        const uint32_t soff = (uint32_t)(s * (STGW * 4));
        #pragma unroll
        for (int kk = 0; kk < 2; kk++) {
            const uint32_t ko = kk * 32;
            uint32_t ahf[4][4], alf[4][4];
            #pragma unroll
            for (int mt = 0; mt < 4; mt++) {
                ldsm4(ahf[mt], AHb + soff + mt * (16 * LDWc * 4) + ko);
                ldsm4(alf[mt], ALb + soff + mt * (16 * LDWc * 4) + ko);
            }
            uint32_t bh01[4], bh23[4], bl01[4], bl23[4];
            ldsm4(bh01, BHb + soff + ko);
            ldsm4(bh23, BHb + soff + 16 * LDWc * 4 + ko);
            ldsm4(bl01, BLb + soff + ko);
            ldsm4(bl23, BLb + soff + 16 * LDWc * 4 + ko);
            #pragma unroll
            for (int mt = 0; mt < 4; mt++) {
                mma16816(acc[mt][0], ahf[mt], &bh01[0]);
                mma16816(acc[mt][1], ahf[mt], &bh01[2]);
                mma16816(acc[mt][2], ahf[mt], &bh23[0]);
                mma16816(acc[mt][3], ahf[mt], &bh23[2]);
                mma16816(acc[mt][0], ahf[mt], &bl01[0]);
                mma16816(acc[mt][1], ahf[mt], &bl01[2]);
                mma16816(acc[mt][2], ahf[mt], &bl23[0]);
                mma16816(acc[mt][3], ahf[mt], &bl23[2]);
                mma16816(acc[mt][0], alf[mt], &bh01[0]);
                mma16816(acc[mt][1], alf[mt], &bh01[2]);
                mma16816(acc[mt][2], alf[mt], &bh23[0]);
                mma16816(acc[mt][3], alf[mt], &bh23[2]);
            }
        }
        // no trailing sync: next store targets the other stage
    }

    if (epi == 0) {
        float* dstbase = Cout + (size_t)m0 * N + n0;
        #pragma unroll
        for (int mt = 0; mt < 4; mt++)
            #pragma unroll
            for (int rr = 0; rr < 2; rr++) {
                int lr = wm + mt * 16 + g + rr * 8;
                float* drow = dstbase + (size_t)lr * N;
                #pragma unroll
                for (int nt = 0; nt < 4; nt++) {
                    int lc = wn + nt * 8 + 2 * t;
                    int gc = n0 + lc;
                    float2 v;
                    v.x = acc[mt][nt][rr*2 + 0] + bias[gc + 0];
                    v.y = acc[mt][nt][rr*2 + 1] + bias[gc + 1];
                    *(float2*)(drow + lc) = v;
                }
            }
    } else {
        int part = n0 >> 11, d2 = n0 & 2047;
        int h = d2 >> 7;
        int bb = m0 >> 11, s0 = m0 & 2047;
        if (part == 2) {
            float* dstbase = g_v + (((size_t)(bb * Hh + h)) * Ss + s0) * HDd;
            #pragma unroll
            for (int mt = 0; mt < 4; mt++)
                #pragma unroll
                for (int rr = 0; rr < 2; rr++) {
                    int lr = wm + mt * 16 + g + rr * 8;
                    float* drow = dstbase + (size_t)lr * HDd;
                    #pragma unroll
                    for (int nt = 0; nt < 4; nt++) {
                        int lc = wn + nt * 8 + 2 * t;
                        int gc = n0 + lc;
                        float2 v;
                        v.x = acc[mt][nt][rr*2 + 0] + bias[gc + 0];
                        v.y = acc[mt][nt][rr*2 + 1] + bias[gc + 1];
                        *(float2*)(drow + lc) = v;
                    }
                }
        } else {
            __nv_bfloat16* basep = (part == 0) ? g_qs : g_ks;
            float scale = (part == 0) ? QSCALE : 1.0f;
            __nv_bfloat16* dstbase = basep + (((size_t)(bb * Hh + h)) * Ss + s0) * (size_t)KQ3;
            #pragma unroll
            for (int mt = 0; mt < 4; mt++)
                #pragma unroll
                for (int rr = 0; rr < 2; rr++) {
                    int lr = wm + mt * 16 + g + rr * 8;
                    uint32_t* drow = (uint32_t*)(dstbase + (size_t)lr * KQ3);
                    #pragma unroll
                    for (int nt = 0; nt < 4; nt++) {
                        int lc = wn + nt * 8 + 2 * t;
                        int gc = n0 + lc;
                        float vx = (acc[mt][nt][rr*2 + 0] + bias[gc + 0]) * scale;
                        float vy = (acc[mt][nt][rr*2 + 1] + bias[gc + 1]) * scale;
                        float hx = __bfloat162float(__float2bfloat16(vx));
                        float hy = __bfloat162float(__float2bfloat16(vy));
                        uint32_t hi2 = pack_bf2(hx, hy);
                        uint32_t lo2 = pack_bf2(vx - hx, vy - hy);
                        int wd = lc >> 1;
                        drow[wd]       = hi2;
                        drow[64 + wd]  = (part == 0) ? hi2 : lo2;
                        drow[128 + wd] = (part == 0) ? lo2 : hi2;
                    }
                }
        }
    }
}

// ---------------- vsplit: g_v -> g_vt (transpose + hi/lo split, once) ----------
#define VS_SMEM (128*132*4)
__global__ __launch_bounds__(256)
void vsplit_kernel()
{
    extern __shared__ float vsm[];   // [128][132]
    const int tid = threadIdx.x;
    const int sch = blockIdx.x;
    const int bh = blockIdx.y;
    const int s0 = sch * 128;

    const float4* src = (const float4*)(g_v + ((size_t)bh * Ss + s0) * HDd);
    for (int idx = tid; idx < 128 * 32; idx += 256) {
        int row = idx >> 5, c4 = idx & 31;
        *(float4*)&vsm[row * 132 + c4 * 4] = src[row * 32 + c4];
    }
    __syncthreads();

    const int d = tid & 127, half = tid >> 7;
    uint32_t* dstb = (uint32_t*)g_vt + ((size_t)(bh * HDd + d) * 3) * (Ss/2) + ((s0 + half * 64) >> 1);
    #pragma unroll
    for (int g8 = 0; g8 < 8; g8++) {
        int sb = half * 64 + g8 * 8;
        float f[8];
        #pragma unroll
        for (int e = 0; e < 8; e++) f[e] = vsm[(sb + e) * 132 + d];
        uint32_t hw[4], lw[4];
        #pragma unroll
        for (int p = 0; p < 4; p++) {
            float a = f[2*p], bq = f[2*p+1];
            float ha = __bfloat162float(__float2bfloat16(a));
            float hb = __bfloat162float(__float2bfloat16(bq));
            hw[p] = pack_bf2(a, bq);
            lw[p] = pack_bf2(a - ha, bq - hb);
        }
        uint4 hv = make_uint4(hw[0], hw[1], hw[2], hw[3]);
        uint4 lv = make_uint4(lw[0], lw[1], lw[2], lw[3]);
        *(uint4*)&dstb[g8 * 4]              = hv;
        *(uint4*)&dstb[(Ss/2) + g8 * 4]     = lv;
        *(uint4*)&dstb[2*(Ss/2) + g8 * 4]   = hv;
    }
}

// ---------------- flash forward: ctx + lse + score spill (ldmatrix) -------------
#define QKLDW 196
#define PVLDW 100
#define FL_QS   0
#define FL_KS   (FL_QS + 64*QKLDW)
#define FL_VT   (FL_KS + 64*QKLDW)
#define FL_PB   (FL_VT + 128*PVLDW)
#define FL_PS   (FL_PB + 64*PVLDW)
#define FL_RM   (FL_PS + 64*68)
#define FL_RL   (FL_RM + 64)
#define FL_RC   (FL_RL + 64)
#define FL_KA   (FL_RC + 64)
#define FL_WORDS (FL_KA + 64)
#define FLASH_SMEM (FL_WORDS*4)

__global__ __launch_bounds__(256, 1)
void flash_kernel()
{
    extern __shared__ uint32_t smw[];
    uint32_t* Qw  = smw + FL_QS;
    uint32_t* Kw  = smw + FL_KS;
    uint32_t* Vtw = smw + FL_VT;
    uint32_t* Pbw = smw + FL_PB;
    float* Ps   = (float*)(smw + FL_PS);
    float* rowM = (float*)(smw + FL_RM);
    float* rowL = (float*)(smw + FL_RL);
    float* rowC = (float*)(smw + FL_RC);
    float* kadd = (float*)(smw + FL_KA);

    const int tid = threadIdx.x;
    const int bh = blockIdx.y;
    const int b = bh >> 4, h = bh & 15;
    const int qt = (int)gridDim.x - 1 - (int)blockIdx.x;
    const int q0 = qt * 64;
    const float slope = exp2f(-0.5f * (float)(h + 1));

    const int w = tid >> 5, l = tid & 31;
    const int wqk = w >> 1;
    const int wn0 = (w & 1) * 32;
    const int wo0 = (w & 1) * 64;
    const int g = l >> 2, t = l & 3;
    const int r0l = 16 * wqk;
    const int sr = tid >> 2, sq = tid & 3;

    const uint32_t aQaddr = smem_u32(Qw)  + ((((r0l + (l & 15)) * QKLDW) + ((l >> 4) << 2)) << 2);
    const uint32_t bKaddr = smem_u32(Kw)  + ((((wn0 + ((l >> 4) << 3) + (l & 7)) * QKLDW) + (((l >> 3) & 1) << 2)) << 2);
    const uint32_t aPaddr = smem_u32(Pbw) + ((((r0l + (l & 15)) * PVLDW) + ((l >> 4) << 2)) << 2);
    const uint32_t bVaddr = smem_u32(Vtw) + ((((wo0 + ((l >> 4) << 3) + (l & 7)) * PVLDW) + (((l >> 3) & 1) << 2)) << 2);

    {
        const int r = tid >> 2, u = tid & 3;
        const uint4* src = (const uint4*)(g_qs + ((size_t)bh * Ss + q0 + r) * KQ3);
        #pragma unroll
        for (int i = 0; i < 12; i++)
            *(uint4*)&Qw[r * QKLDW + (u + 4*i) * 4] = src[u + 4*i];
    }
    if (tid < 64) { rowM[tid] = -1e30f; rowL[tid] = 0.0f; }

    float O[8][4];
    #pragma unroll
    for (int i = 0; i < 8; i++)
        #pragma unroll
        for (int q = 0; q < 4; q++) O[i][q] = 0.0f;

    for (int kt = 0; kt <= qt; kt++) {
        const int k0 = kt * 64;
        float* scp = g_sc + (((size_t)b * NTRI + (size_t)(qt*(qt+1)/2 + kt)) * Hh + h) * 4096;
        __syncthreads();
        {
            const int r = tid >> 2, u = tid & 3;
            const uint4* src = (const uint4*)(g_ks + ((size_t)bh * Ss + k0 + r) * KQ3);
            #pragma unroll
            for (int i = 0; i < 12; i++)
                *(uint4*)&Kw[r * QKLDW + (u + 4*i) * 4] = src[u + 4*i];
        }
        {
            const int r2 = tid >> 1, u2 = tid & 1;
            const uint32_t* vtb = (const uint32_t*)g_vt + ((size_t)(bh * HDd + r2) * 3) * (Ss/2) + (k0 >> 1);
            #pragma unroll
            for (int i = 0; i < 12; i++) {
                int wpos = (u2 + 2*i) * 4;
                int seg = wpos >> 5, wseg = wpos & 31;
                *(uint4*)&Vtw[r2 * PVLDW + wpos] = *(const uint4*)(vtb + (size_t)seg * (Ss/2) + wseg);
            }
        }
        if (tid < 64) kadd[tid] = g_kpm_add[b * Ss + k0 + tid];
        __syncthreads();

        float sacc[4][4];
        #pragma unroll
        for (int i = 0; i < 4; i++)
            #pragma unroll
            for (int q = 0; q < 4; q++) sacc[i][q] = 0.0f;
        #pragma unroll 8
        for (int kk = 0; kk < 24; kk++) {
            uint32_t af[4], b01[4], b23[4];
            ldsm4(af, aQaddr + kk * 32);
            ldsm4(b01, bKaddr + kk * 32);
            ldsm4(b23, bKaddr + (16 * QKLDW << 2) + kk * 32);
            mma16816(sacc[0], af, &b01[0]);
            mma16816(sacc[1], af, &b01[2]);
            mma16816(sacc[2], af, &b23[0]);
            mma16816(sacc[3], af, &b23[2]);
        }
        #pragma unroll
        for (int nt = 0; nt < 4; nt++) {
            int colb = wn0 + nt * 8 + 2 * t;
            int kj0 = k0 + colb;
            float ka0 = kadd[colb], ka1 = kadd[colb + 1];
            int qi0 = q0 + r0l + g;
            int qi1 = qi0 + 8;
            float2 s0, s1;
            s0.x = (kj0     > qi0) ? -1e30f : sacc[nt][0] + (float)(kj0     - qi0) * slope + ka0;
            s0.y = (kj0 + 1 > qi0) ? -1e30f : sacc[nt][1] + (float)(kj0 + 1 - qi0) * slope + ka1;
            s1.x = (kj0     > qi1) ? -1e30f : sacc[nt][2] + (float)(kj0     - qi1) * slope + ka0;
            s1.y = (kj0 + 1 > qi1) ? -1e30f : sacc[nt][3] + (float)(kj0 + 1 - qi1) * slope + ka1;
            *(float2*)&Ps[(r0l + g    ) * 68 + colb] = s0;
            *(float2*)&Ps[(r0l + g + 8) * 68 + colb] = s1;
            *(float2*)&scp[(r0l + g    ) * 64 + colb] = s0;
            *(float2*)&scp[(r0l + g + 8) * 64 + colb] = s1;
        }
        __syncthreads();

        {
            float sv[16];
            const float4* pr = (const float4*)(Ps + sr * 68 + sq * 16);
            #pragma unroll
            for (int i = 0; i < 4; i++) {
                float4 v = pr[i];
                sv[4*i+0] = v.x; sv[4*i+1] = v.y; sv[4*i+2] = v.z; sv[4*i+3] = v.w;
            }
            float mt = -1e30f;
            #pragma unroll
            for (int j = 0; j < 16; j++) mt = fmaxf(mt, sv[j]);
            mt = fmaxf(mt, __shfl_xor_sync(0xffffffffu, mt, 1));
            mt = fmaxf(mt, __shfl_xor_sync(0xffffffffu, mt, 2));
            float mold = rowM[sr];
            float mnew = fmaxf(mold, mt);
            float p[16];
            if (mnew < -1e29f) {
                #pragma unroll
                for (int j = 0; j < 16; j++) p[j] = 0.0f;
                if (sq == 0) rowC[sr] = 1.0f;
            } else {
                float corr = __expf(mold - mnew);
                float sum = 0.0f;
                #pragma unroll
                for (int j = 0; j < 16; j++) { p[j] = __expf(sv[j] - mnew); sum += p[j]; }
                sum += __shfl_xor_sync(0xffffffffu, sum, 1);
                sum += __shfl_xor_sync(0xffffffffu, sum, 2);
                if (sq == 0) {
                    rowM[sr] = mnew;
                    rowL[sr] = rowL[sr] * corr + sum;
                    rowC[sr] = corr;
                }
            }
            uint32_t* pw = Pbw + sr * PVLDW + sq * 8;
            #pragma unroll
            for (int j = 0; j < 8; j++) {
                float a = p[2*j], bq = p[2*j+1];
                float ha = __bfloat162float(__float2bfloat16(a));
                float hb = __bfloat162float(__float2bfloat16(bq));
                uint32_t hw = pack_bf2(a, bq);
                uint32_t lw = pack_bf2(a - ha, bq - hb);
                pw[j]      = hw;
                pw[32 + j] = hw;
                pw[64 + j] = lw;
            }
        }
        __syncthreads();

        {
            float cf0 = rowC[r0l + g], cf1 = rowC[r0l + g + 8];
            #pragma unroll
            for (int nt = 0; nt < 8; nt++) {
                O[nt][0] *= cf0; O[nt][1] *= cf0;
                O[nt][2] *= cf1; O[nt][3] *= cf1;
            }
        }
        #pragma unroll 4
        for (int kk = 0; kk < 12; kk++) {
            uint32_t af[4];
            ldsm4(af, aPaddr + kk * 32);
            #pragma unroll
            for (int p = 0; p < 4; p++) {
                uint32_t bv[4];
                ldsm4(bv, bVaddr + p * (16 * PVLDW << 2) + kk * 32);
                mma16816(O[p*2    ], af, &bv[0]);
                mma16816(O[p*2 + 1], af, &bv[2]);
            }
        }
    }

    __syncthreads();
    if (tid < 64) {
        float lsum = rowL[tid];
        rowC[tid] = 1.0f / lsum;
        g_lse[(size_t)bh * Ss + q0 + tid] = rowM[tid] + logf(lsum);
    }
    __syncthreads();
    {
        float invl0 = rowC[r0l + g], invl1 = rowC[r0l + g + 8];
        float* d0 = g_ctx + ((size_t)(b * Ss + q0 + r0l + g    )) * Dd + h * HDd;
        float* d1 = g_ctx + ((size_t)(b * Ss + q0 + r0l + g + 8)) * Dd + h * HDd;
        #pragma unroll
        for (int nt = 0; nt < 8; nt++) {
            int col = wo0 + nt * 8 + 2 * t;
            *(float2*)(d0 + col) = make_float2(O[nt][0] * invl0, O[nt][1] * invl0);
            *(float2*)(d1 + col) = make_float2(O[nt][2] * invl1, O[nt][3] * invl1);
        }
    }
}

// ---------------- avg_attn: stream spilled scores ----------------
__global__ __launch_bounds__(256)
void avg_kernel(float* __restrict__ avg)
{
    const int tid = threadIdx.x;
    const int b = blockIdx.z, qt = blockIdx.y, kt = blockIdx.x;
    const int q0 = qt * 64, k0 = kt * 64;
    const int r = tid >> 2, c0 = (tid & 3) * 16;
    float* drow = avg + ((size_t)(b * Ss + q0 + r)) * Ss + k0 + c0;

    if (kt > qt) {
        float4 z = make_float4(0.f, 0.f, 0.f, 0.f);
        #pragma unroll
        for (int i = 0; i < 4; i++) ((float4*)drow)[i] = z;
        return;
    }

    size_t tbase = ((size_t)b * NTRI + (size_t)(qt*(qt+1)/2 + kt)) * Hh * 4096;
    float acc[16];
    #pragma unroll
    for (int j = 0; j < 16; j++) acc[j] = 0.0f;

    for (int h = 0; h < Hh; h++) {
        float lse = g_lse[((size_t)(b * Hh + h)) * Ss + q0 + r];
        const float4* sp = (const float4*)(g_sc + tbase + (size_t)h * 4096 + r * 64 + c0);
        #pragma unroll
        for (int i = 0; i < 4; i++) {
            float4 s4 = sp[i];
            acc[4*i+0] += __expf(s4.x - lse);
            acc[4*i+1] += __expf(s4.y - lse);
            acc[4*i+2] += __expf(s4.z - lse);
            acc[4*i+3] += __expf(s4.w - lse);
        }
    }
    #pragma unroll
    for (int i = 0; i < 4; i++) {
        float4 v = make_float4(acc[4*i+0]*0.0625f, acc[4*i+1]*0.0625f,
                               acc[4*i+2]*0.0625f, acc[4*i+3]*0.0625f);
        ((float4*)drow)[i] = v;
    }
}

// ---------------- launch ----------------
extern "C" void kernel_launch(void* const* d_in, const int* in_sizes, int n_in,
                              void* d_out, int out_size)
{
    const float* x    = (const float*)d_in[0];
    const void*  kpm  = d_in[1];
    const float* inw  = (const float*)d_in[3];
    const float* inb  = (const float*)d_in[4];
    const float* outw = (const float*)d_in[5];
    const float* outb = (const float*)d_in[6];

    float* out = (float*)d_out;
    float* avg = out + OUT_ELEMS;

    cudaFuncSetAttribute(gemm_mma_kernel, cudaFuncAttributeMaxDynamicSharedMemorySize, GM_SMEM);
    cudaFuncSetAttribute(flash_kernel, cudaFuncAttributeMaxDynamicSharedMemorySize, FLASH_SMEM);
    cudaFuncSetAttribute(vsplit_kernel, cudaFuncAttributeMaxDynamicSharedMemorySize, VS_SMEM);

    mask_norm_kernel<<<1, 256>>>(kpm, BSr);

    {
        long long n4;
        n4 = (long long)BSr * Dd / 4;
        split_kernel<<<(unsigned)((n4 + 255) / 256), 256>>>(x, n4, 0);
        n4 = (long long)3 * Dd * Dd / 4;
        split_kernel<<<(unsigned)((n4 + 255) / 256), 256>>>(inw, n4, 1);
        n4 = (long long)Dd * Dd / 4;
        split_kernel<<<(unsigned)((n4 + 255) / 256), 256>>>(outw, n4, 2);
    }

    // QKV projection (q/k split + v fp32)
    gemm_mma_kernel<<<dim3(3*Dd/128, BSr/128), 256, GM_SMEM>>>(0, inb, nullptr, 3*Dd, 1);

    // one-shot V transpose+split
    vsplit_kernel<<<dim3(Ss/128, Bb*Hh), 256, VS_SMEM>>>();

    // flash attention (spills scores, writes g_ctx fp32)
    flash_kernel<<<dim3(Ss/64, Bb*Hh), 256, FLASH_SMEM>>>();

    // ---- fork: avg (stream s2) || ctx-split + out-proj (stream 0) ----
    cudaStream_t s2;
    cudaStreamCreateWithFlags(&s2, cudaStreamNonBlocking);
    cudaEvent_t e1, e2;
    cudaEventCreateWithFlags(&e1, cudaEventDisableTiming);
    cudaEventCreateWithFlags(&e2, cudaEventDisableTiming);

    cudaEventRecord(e1, 0);
    cudaStreamWaitEvent(s2, e1, 0);
    avg_kernel<<<dim3(NT, NT, Bb), 256, 0, s2>>>(avg);
    cudaEventRecord(e2, s2);

    {
        long long n4 = (long long)BSr * Dd / 4;
        split_kernel<<<(unsigned)((n4 + 255) / 256), 256>>>(nullptr, n4, 3);
    }
    gemm_mma_kernel<<<dim3(Dd/128, BSr/128), 256, GM_SMEM>>>(1, outb, out, Dd, 0);

    cudaStreamWaitEvent(0, e2, 0);
    // s2/e1/e2 intentionally not destroyed (graph capture safety; replays don't re-run host code)
}

// round 17
// speedup vs baseline: 1.1685x; 1.1685x over previous
#include <cuda_runtime.h>
#include <cuda_bf16.h>
#include <math.h>
#include <stdint.h>

#define Bb 2
#define Ss 2048
#define Dd 2048
#define Hh 16
#define HDd 128
#define BSr (Bb*Ss)
#define Kd 2048
#define KQ2 (2*HDd)                 // 256: q/k row = [h|l]
#define NT 32
#define NTRI 528
#define OUT_ELEMS (Bb*Ss*Dd)
#define QSCALE 0.08838834764831843f

// ---------------- scratch (device globals; referenced only from device code) ----
__device__ float g_v[Bb*Hh*Ss*HDd];
__device__ float g_ctx[Bb*Ss*Dd];
__device__ float g_lse[Bb*Hh*Ss];
__device__ float g_kpm_add[BSr];
__device__ float g_sc[(size_t)Bb*NTRI*Hh*4096];
__device__ __nv_bfloat16 g_qs[(size_t)Bb*Hh*Ss*KQ2];  // [h|l], pre-scaled
__device__ __nv_bfloat16 g_ks[(size_t)Bb*Hh*Ss*KQ2];  // [h|l]
__device__ __nv_bfloat16 g_vt[(size_t)Bb*Hh*HDd*2*Ss];// V^T [bh][d][h|l over s]
__device__ __nv_bfloat16 g_xh[(size_t)BSr*Dd];
__device__ __nv_bfloat16 g_xl[(size_t)BSr*Dd];
__device__ __nv_bfloat16 g_wih[(size_t)3*Dd*Dd];
__device__ __nv_bfloat16 g_wil[(size_t)3*Dd*Dd];
__device__ __nv_bfloat16 g_woh[(size_t)Dd*Dd];
__device__ __nv_bfloat16 g_wol[(size_t)Dd*Dd];
__device__ __nv_bfloat16 g_cth[(size_t)BSr*Dd];
__device__ __nv_bfloat16 g_ctl[(size_t)BSr*Dd];

__device__ __forceinline__ void mma16816(float* c, const uint32_t* a, const uint32_t* b) {
    asm volatile("mma.sync.aligned.m16n8k16.row.col.f32.bf16.bf16.f32 "
        "{%0,%1,%2,%3}, {%4,%5,%6,%7}, {%8,%9}, {%0,%1,%2,%3};"
        : "+f"(c[0]), "+f"(c[1]), "+f"(c[2]), "+f"(c[3])
        : "r"(a[0]), "r"(a[1]), "r"(a[2]), "r"(a[3]), "r"(b[0]), "r"(b[1]));
}
__device__ __forceinline__ void ldsm4(uint32_t* r, uint32_t saddr) {
    asm volatile("ldmatrix.sync.aligned.m8n8.x4.shared.b16 {%0,%1,%2,%3}, [%4];"
        : "=r"(r[0]), "=r"(r[1]), "=r"(r[2]), "=r"(r[3]) : "r"(saddr));
}
__device__ __forceinline__ uint32_t pack_bf2(float x, float y) {
    __nv_bfloat162 p = __floats2bfloat162_rn(x, y);
    return *(uint32_t*)&p;
}
__device__ __forceinline__ uint32_t smem_u32(const void* p) {
    uint32_t a;
    asm("{ .reg .u64 t; cvta.to.shared.u64 t, %1; cvt.u32.u64 %0, t; }" : "=r"(a) : "l"(p));
    return a;
}

// ---------------- key_padding_mask normalizer ----------------
__global__ void mask_norm_kernel(const void* kpm, int n)
{
    __shared__ int s_mode;
    __shared__ int c_upper, c_lower, c_fbad;
    const unsigned char* bp = (const unsigned char*)kpm;
    const float* fp = (const float*)kpm;
    int tid = threadIdx.x;
    if (tid == 0) { c_upper = 0; c_lower = 0; c_fbad = 0; }
    __syncthreads();
    for (int i = tid; i < n; i += blockDim.x) {
        unsigned char v = bp[i];
        if (v) { if (i & 3) atomicAdd(&c_upper, 1); else atomicAdd(&c_lower, 1); }
    }
    for (int i = tid; i < n / 4; i += blockDim.x) {
        float v = fp[i];
        if (!(v == 0.0f || v == 1.0f)) atomicAdd(&c_fbad, 1);
    }
    __syncthreads();
    if (tid == 0) {
        if (c_upper == 0 && c_lower == 0) s_mode = 2;
        else if (c_fbad == 0) s_mode = 0;
        else if (c_upper == 0) s_mode = 1;
        else s_mode = 2;
    }
    __syncthreads();
    int mode = s_mode;
    for (int i = tid; i < n; i += blockDim.x) {
        bool keep;
        if (mode == 0)      keep = (fp[i] != 0.0f);
        else if (mode == 1) keep = (((const int*)kpm)[i] != 0);
        else                keep = (bp[i] != 0);
        g_kpm_add[i] = keep ? 0.0f : -1e30f;
    }
}

// ---------------- fp32 -> bf16 h/l component split ----------------
__global__ void split_kernel(const float* __restrict__ src, long long n4, int dsel)
{
    long long i = (long long)blockIdx.x * blockDim.x + threadIdx.x;
    if (i >= n4) return;
    if (src == nullptr) src = g_ctx;
    __nv_bfloat16* dh = (dsel == 0) ? g_xh : (dsel == 1) ? g_wih
                      : (dsel == 2) ? g_woh : g_cth;
    __nv_bfloat16* dl = (dsel == 0) ? g_xl : (dsel == 1) ? g_wil
                      : (dsel == 2) ? g_wol : g_ctl;
    long long e = i * 4;
    float4 v = *(const float4*)(src + e);
    float f[4] = {v.x, v.y, v.z, v.w};
    __nv_bfloat16 h[4], l[4];
    #pragma unroll
    for (int j = 0; j < 4; j++) {
        h[j] = __float2bfloat16(f[j]);
        l[j] = __float2bfloat16(f[j] - __bfloat162float(h[j]));
    }
    uint32_t hp0 = ((uint32_t)__bfloat16_as_ushort(h[1]) << 16) | __bfloat16_as_ushort(h[0]);
    uint32_t hp1 = ((uint32_t)__bfloat16_as_ushort(h[3]) << 16) | __bfloat16_as_ushort(h[2]);
    uint32_t lp0 = ((uint32_t)__bfloat16_as_ushort(l[1]) << 16) | __bfloat16_as_ushort(l[0]);
    uint32_t lp1 = ((uint32_t)__bfloat16_as_ushort(l[3]) << 16) | __bfloat16_as_ushort(l[2]);
    *(uint2*)(dh + e) = make_uint2(hp0, hp1);
    *(uint2*)(dl + e) = make_uint2(lp0, lp1);
}

// ---------------- bf16 mma.sync NT GEMM (R15 loop; chunk-mapped dedup sources) ---
// Logical K' = 6144 = [Ah|Ah|Al] x [Bh|Bl|Bh]; physical arrays hold h/l once.
#define LDW 36
#define HSTG 4608
#define STGW (2*HSTG)
#define GM_SMEM (2*STGW*4)           // 73728 bytes

__global__ __launch_bounds__(256)
void gemm_mma_kernel(int absel, const float* __restrict__ bias, float* __restrict__ Cout,
                     int N, int epi)
{
    extern __shared__ uint32_t gsm[];

    const uint32_t* ahw;
    const uint32_t* alw;
    const uint32_t* bhw;
    const uint32_t* blw;
    {
        const int m0i = blockIdx.y * 128, n0i = blockIdx.x * 128;
        const __nv_bfloat16* AH = (absel == 0) ? g_xh  : g_cth;
        const __nv_bfloat16* AL = (absel == 0) ? g_xl  : g_ctl;
        const __nv_bfloat16* BH = (absel == 0) ? g_wih : g_woh;
        const __nv_bfloat16* BL = (absel == 0) ? g_wil : g_wol;
        ahw = (const uint32_t*)(AH + (size_t)m0i * Kd);
        alw = (const uint32_t*)(AL + (size_t)m0i * Kd);
        bhw = (const uint32_t*)(BH + (size_t)n0i * Kd);
        blw = (const uint32_t*)(BL + (size_t)n0i * Kd);
    }

    const int tid = threadIdx.x;
    const int m0 = blockIdx.y * 128, n0 = blockIdx.x * 128;
    const int NCH = 96;                // logical 64-el chunks
    const int wstride = Kd / 2;        // 1024 words per component row

    const int lrow0 = tid >> 3;
    const int lw    = (tid & 7) * 4;
    const int w = tid >> 5, l = tid & 31;
    const int wm = (w >> 2) * 64, wn = (w & 3) * 32;
    const int g = l >> 2, t = l & 3;

    const uint32_t aAddr0 = smem_u32(gsm) + ((((wm + (l & 15)) * LDW) + ((l >> 4) << 2)) << 2);
    const uint32_t bAddr0 = smem_u32(gsm) + ((HSTG + ((wn + ((l >> 4) << 3) + (l & 7)) * LDW) + (((l >> 3) & 1) << 2)) << 2);

    float acc[4][4][4];
    #pragma unroll
    for (int i = 0; i < 4; i++)
        #pragma unroll
        for (int j = 0; j < 4; j++)
            #pragma unroll
            for (int q = 0; q < 4; q++) acc[i][j][q] = 0.0f;

    // chunk -> (source, offset) mapping
    #define GMAP(c, asrc, aco, bsrc, bco) \
        const uint32_t* asrc = ((c) < 64) ? ahw : alw; \
        const int aco = ((c) < 64) ? (((c) & 31) * 32) : (((c) - 64) * 32); \
        const uint32_t* bsrc = ((c) < 32 || (c) >= 64) ? bhw : blw; \
        const int bco = ((c) < 32) ? ((c) * 32) : (((c) < 64) ? (((c) - 32) * 32) : (((c) - 64) * 32));

    uint4 ra[4], rb[4];
    {
        GMAP(0, as_, ao_, bs_, bo_);
        #pragma unroll
        for (int i = 0; i < 4; i++) {
            int row = lrow0 + i * 32;
            ra[i] = *(const uint4*)&as_[(size_t)row * wstride + ao_ + lw];
            rb[i] = *(const uint4*)&bs_[(size_t)row * wstride + bo_ + lw];
        }
    }

    for (int c = 0; c < NCH; c++) {
        const int s = c & 1;
        uint32_t* Asw = gsm + s * STGW;
        uint32_t* Bsw = Asw + HSTG;
        #pragma unroll
        for (int i = 0; i < 4; i++) {
            int row = lrow0 + i * 32;
            *(uint4*)&Asw[row * LDW + lw] = ra[i];
            *(uint4*)&Bsw[row * LDW + lw] = rb[i];
        }
        __syncthreads();
        if (c + 1 < NCH) {
            const int cn = c + 1;
            GMAP(cn, as_, ao_, bs_, bo_);
            #pragma unroll
            for (int i = 0; i < 4; i++) {
                int row = lrow0 + i * 32;
                ra[i] = *(const uint4*)&as_[(size_t)row * wstride + ao_ + lw];
                rb[i] = *(const uint4*)&bs_[(size_t)row * wstride + bo_ + lw];
            }
        }
        const uint32_t soff = s * (STGW * 4);
        #pragma unroll
        for (int kk = 0; kk < 4; kk++) {
            uint32_t af[4][4];
            #pragma unroll
            for (int mt = 0; mt < 4; mt++)
                ldsm4(af[mt], aAddr0 + soff + mt * (16 * LDW * 4) + kk * 32);
            uint32_t b01[4], b23[4];
            ldsm4(b01, bAddr0 + soff + kk * 32);
            ldsm4(b23, bAddr0 + soff + 16 * LDW * 4 + kk * 32);
            #pragma unroll
            for (int mt = 0; mt < 4; mt++) {
                mma16816(acc[mt][0], af[mt], &b01[0]);
                mma16816(acc[mt][1], af[mt], &b01[2]);
                mma16816(acc[mt][2], af[mt], &b23[0]);
                mma16816(acc[mt][3], af[mt], &b23[2]);
            }
        }
    }

    if (epi == 0) {
        float* dstbase = Cout + (size_t)m0 * N + n0;
        #pragma unroll
        for (int mt = 0; mt < 4; mt++)
            #pragma unroll
            for (int rr = 0; rr < 2; rr++) {
                int lr = wm + mt * 16 + g + rr * 8;
                float* drow = dstbase + (size_t)lr * N;
                #pragma unroll
                for (int nt = 0; nt < 4; nt++) {
                    int lc = wn + nt * 8 + 2 * t;
                    int gc = n0 + lc;
                    float2 v;
                    v.x = acc[mt][nt][rr*2 + 0] + bias[gc + 0];
                    v.y = acc[mt][nt][rr*2 + 1] + bias[gc + 1];
                    *(float2*)(drow + lc) = v;
                }
            }
    } else {
        int part = n0 >> 11, d2 = n0 & 2047;
        int h = d2 >> 7;
        int bb = m0 >> 11, s0 = m0 & 2047;
        if (part == 2) {
            float* dstbase = g_v + (((size_t)(bb * Hh + h)) * Ss + s0) * HDd;
            #pragma unroll
            for (int mt = 0; mt < 4; mt++)
                #pragma unroll
                for (int rr = 0; rr < 2; rr++) {
                    int lr = wm + mt * 16 + g + rr * 8;
                    float* drow = dstbase + (size_t)lr * HDd;
                    #pragma unroll
                    for (int nt = 0; nt < 4; nt++) {
                        int lc = wn + nt * 8 + 2 * t;
                        int gc = n0 + lc;
                        float2 v;
                        v.x = acc[mt][nt][rr*2 + 0] + bias[gc + 0];
                        v.y = acc[mt][nt][rr*2 + 1] + bias[gc + 1];
                        *(float2*)(drow + lc) = v;
                    }
                }
        } else {
            __nv_bfloat16* basep = (part == 0) ? g_qs : g_ks;
            float scale = (part == 0) ? QSCALE : 1.0f;
            __nv_bfloat16* dstbase = basep + (((size_t)(bb * Hh + h)) * Ss + s0) * (size_t)KQ2;
            #pragma unroll
            for (int mt = 0; mt < 4; mt++)
                #pragma unroll
                for (int rr = 0; rr < 2; rr++) {
                    int lr = wm + mt * 16 + g + rr * 8;
                    uint32_t* drow = (uint32_t*)(dstbase + (size_t)lr * KQ2);
                    #pragma unroll
                    for (int nt = 0; nt < 4; nt++) {
                        int lc = wn + nt * 8 + 2 * t;
                        int gc = n0 + lc;
                        float vx = (acc[mt][nt][rr*2 + 0] + bias[gc + 0]) * scale;
                        float vy = (acc[mt][nt][rr*2 + 1] + bias[gc + 1]) * scale;
                        float hx = __bfloat162float(__float2bfloat16(vx));
                        float hy = __bfloat162float(__float2bfloat16(vy));
                        int wd = lc >> 1;
                        drow[wd]      = pack_bf2(hx, hy);
                        drow[64 + wd] = pack_bf2(vx - hx, vy - hy);
                    }
                }
        }
    }
}

// ---------------- vsplit: g_v -> g_vt ([h|l] over s) ----------
#define VS_SMEM (128*132*4)
__global__ __launch_bounds__(256)
void vsplit_kernel()
{
    extern __shared__ float vsm[];   // [128][132]
    const int tid = threadIdx.x;
    const int sch = blockIdx.x;
    const int bh = blockIdx.y;
    const int s0 = sch * 128;

    const float4* src = (const float4*)(g_v + ((size_t)bh * Ss + s0) * HDd);
    for (int idx = tid; idx < 128 * 32; idx += 256) {
        int row = idx >> 5, c4 = idx & 31;
        *(float4*)&vsm[row * 132 + c4 * 4] = src[row * 32 + c4];
    }
    __syncthreads();

    const int d = tid & 127, half = tid >> 7;
    uint32_t* dstb = (uint32_t*)g_vt + ((size_t)(bh * HDd + d) * 2) * (Ss/2) + ((s0 + half * 64) >> 1);
    #pragma unroll
    for (int g8 = 0; g8 < 8; g8++) {
        int sb = half * 64 + g8 * 8;
        float f[8];
        #pragma unroll
        for (int e = 0; e < 8; e++) f[e] = vsm[(sb + e) * 132 + d];
        uint32_t hw[4], lw[4];
        #pragma unroll
        for (int p = 0; p < 4; p++) {
            float a = f[2*p], bq = f[2*p+1];
            float ha = __bfloat162float(__float2bfloat16(a));
            float hb = __bfloat162float(__float2bfloat16(bq));
            hw[p] = pack_bf2(a, bq);
            lw[p] = pack_bf2(a - ha, bq - hb);
        }
        *(uint4*)&dstb[g8 * 4]          = make_uint4(hw[0], hw[1], hw[2], hw[3]);
        *(uint4*)&dstb[(Ss/2) + g8 * 4] = make_uint4(lw[0], lw[1], lw[2], lw[3]);
    }
}

// ---------------- flash forward: dedup smem + kk-mapped ldmatrix ----------------
#define QKLDW2 132
#define PVLDW2 68
#define FL_QS   0
#define FL_KS   (FL_QS + 64*QKLDW2)
#define FL_VT   (FL_KS + 64*QKLDW2)
#define FL_PB   (FL_VT + 128*PVLDW2)
#define FL_PS   (FL_PB + 64*PVLDW2)
#define FL_RM   (FL_PS + 64*68)
#define FL_RL   (FL_RM + 64)
#define FL_RC   (FL_RL + 64)
#define FL_KA   (FL_RC + 64)
#define FL_WORDS (FL_KA + 64)
#define FLASH_SMEM (FL_WORDS*4)

__global__ __launch_bounds__(256, 1)
void flash_kernel()
{
    extern __shared__ uint32_t smw[];
    uint32_t* Qw  = smw + FL_QS;
    uint32_t* Kw  = smw + FL_KS;
    uint32_t* Vtw = smw + FL_VT;
    uint32_t* Pbw = smw + FL_PB;
    float* Ps   = (float*)(smw + FL_PS);
    float* rowM = (float*)(smw + FL_RM);
    float* rowL = (float*)(smw + FL_RL);
    float* rowC = (float*)(smw + FL_RC);
    float* kadd = (float*)(smw + FL_KA);

    const int tid = threadIdx.x;
    const int bh = blockIdx.y;
    const int b = bh >> 4, h = bh & 15;
    const int qt = (int)gridDim.x - 1 - (int)blockIdx.x;
    const int q0 = qt * 64;
    const float slope = exp2f(-0.5f * (float)(h + 1));

    const int w = tid >> 5, l = tid & 31;
    const int wqk = w >> 1;
    const int wn0 = (w & 1) * 32;
    const int wo0 = (w & 1) * 64;
    const int g = l >> 2, t = l & 3;
    const int r0l = 16 * wqk;
    const int sr = tid >> 2, sq = tid & 3;

    const uint32_t aQaddr = smem_u32(Qw)  + ((((r0l + (l & 15)) * QKLDW2) + ((l >> 4) << 2)) << 2);
    const uint32_t bKaddr = smem_u32(Kw)  + ((((wn0 + ((l >> 4) << 3) + (l & 7)) * QKLDW2) + (((l >> 3) & 1) << 2)) << 2);
    const uint32_t aPaddr = smem_u32(Pbw) + ((((r0l + (l & 15)) * PVLDW2) + ((l >> 4) << 2)) << 2);
    const uint32_t bVaddr = smem_u32(Vtw) + ((((wo0 + ((l >> 4) << 3) + (l & 7)) * PVLDW2) + (((l >> 3) & 1) << 2)) << 2);

    {   // Q tile: 64 rows x 32 uint4 ([h|l])
        const int r = tid >> 2, u = tid & 3;
        const uint4* src = (const uint4*)(g_qs + ((size_t)bh * Ss + q0 + r) * KQ2);
        #pragma unroll
        for (int i = 0; i < 8; i++)
            *(uint4*)&Qw[r * QKLDW2 + (u + 4*i) * 4] = src[u + 4*i];
    }
    if (tid < 64) { rowM[tid] = -1e30f; rowL[tid] = 0.0f; }

    float O[8][4];
    #pragma unroll
    for (int i = 0; i < 8; i++)
        #pragma unroll
        for (int q = 0; q < 4; q++) O[i][q] = 0.0f;

    for (int kt = 0; kt <= qt; kt++) {
        const int k0 = kt * 64;
        float* scp = g_sc + (((size_t)b * NTRI + (size_t)(qt*(qt+1)/2 + kt)) * Hh + h) * 4096;
        __syncthreads();
        {   // K tile
            const int r = tid >> 2, u = tid & 3;
            const uint4* src = (const uint4*)(g_ks + ((size_t)bh * Ss + k0 + r) * KQ2);
            #pragma unroll
            for (int i = 0; i < 8; i++)
                *(uint4*)&Kw[r * QKLDW2 + (u + 4*i) * 4] = src[u + 4*i];
        }
        {   // V^T tile: 128 rows x 16 uint4 ([h|l])
            const int r2 = tid >> 1, u2 = tid & 1;
            const uint32_t* vtb = (const uint32_t*)g_vt + ((size_t)(bh * HDd + r2) * 2) * (Ss/2) + (k0 >> 1);
            #pragma unroll
            for (int i = 0; i < 8; i++) {
                int wpos = (u2 + 2*i) * 4;
                int seg = wpos >> 5, wseg = wpos & 31;
                *(uint4*)&Vtw[r2 * PVLDW2 + wpos] = *(const uint4*)(vtb + (size_t)seg * (Ss/2) + wseg);
            }
        }
        if (tid < 64) kadd[tid] = g_kpm_add[b * Ss + k0 + tid];
        __syncthreads();

        // ---- QK^T: logical K'=384 via kk-maps over [h|l] tiles ----
        float sacc[4][4];
        #pragma unroll
        for (int i = 0; i < 4; i++)
            #pragma unroll
            for (int q = 0; q < 4; q++) sacc[i][q] = 0.0f;
        #pragma unroll
        for (int kk = 0; kk < 24; kk++) {
            const int kkA = (kk < 16) ? (kk & 7) : (kk - 8);   // Q: [h|h|l]
            const int kkB = (kk < 16) ? kk : (kk - 16);        // K: [h|l|h]
            uint32_t af[4], b01[4], b23[4];
            ldsm4(af, aQaddr + kkA * 32);
            ldsm4(b01, bKaddr + kkB * 32);
            ldsm4(b23, bKaddr + (16 * QKLDW2 << 2) + kkB * 32);
            mma16816(sacc[0], af, &b01[0]);
            mma16816(sacc[1], af, &b01[2]);
            mma16816(sacc[2], af, &b23[0]);
            mma16816(sacc[3], af, &b23[2]);
        }
        #pragma unroll
        for (int nt = 0; nt < 4; nt++) {
            int colb = wn0 + nt * 8 + 2 * t;
            int kj0 = k0 + colb;
            float ka0 = kadd[colb], ka1 = kadd[colb + 1];
            int qi0 = q0 + r0l + g;
            int qi1 = qi0 + 8;
            float2 s0, s1;
            s0.x = (kj0     > qi0) ? -1e30f : sacc[nt][0] + (float)(kj0     - qi0) * slope + ka0;
            s0.y = (kj0 + 1 > qi0) ? -1e30f : sacc[nt][1] + (float)(kj0 + 1 - qi0) * slope + ka1;
            s1.x = (kj0     > qi1) ? -1e30f : sacc[nt][2] + (float)(kj0     - qi1) * slope + ka0;
            s1.y = (kj0 + 1 > qi1) ? -1e30f : sacc[nt][3] + (float)(kj0 + 1 - qi1) * slope + ka1;
            *(float2*)&Ps[(r0l + g    ) * 68 + colb] = s0;
            *(float2*)&Ps[(r0l + g + 8) * 68 + colb] = s1;
            *(float2*)&scp[(r0l + g    ) * 64 + colb] = s0;
            *(float2*)&scp[(r0l + g + 8) * 64 + colb] = s1;
        }
        __syncthreads();

        // ---- parallel online softmax + P split ([h|l] only) ----
        {
            float sv[16];
            const float4* pr = (const float4*)(Ps + sr * 68 + sq * 16);
            #pragma unroll
            for (int i = 0; i < 4; i++) {
                float4 v = pr[i];
                sv[4*i+0] = v.x; sv[4*i+1] = v.y; sv[4*i+2] = v.z; sv[4*i+3] = v.w;
            }
            float mt = -1e30f;
            #pragma unroll
            for (int j = 0; j < 16; j++) mt = fmaxf(mt, sv[j]);
            mt = fmaxf(mt, __shfl_xor_sync(0xffffffffu, mt, 1));
            mt = fmaxf(mt, __shfl_xor_sync(0xffffffffu, mt, 2));
            float mold = rowM[sr];
            float mnew = fmaxf(mold, mt);
            float p[16];
            if (mnew < -1e29f) {
                #pragma unroll
                for (int j = 0; j < 16; j++) p[j] = 0.0f;
                if (sq == 0) rowC[sr] = 1.0f;
            } else {
                float corr = __expf(mold - mnew);
                float sum = 0.0f;
                #pragma unroll
                for (int j = 0; j < 16; j++) { p[j] = __expf(sv[j] - mnew); sum += p[j]; }
                sum += __shfl_xor_sync(0xffffffffu, sum, 1);
                sum += __shfl_xor_sync(0xffffffffu, sum, 2);
                if (sq == 0) {
                    rowM[sr] = mnew;
                    rowL[sr] = rowL[sr] * corr + sum;
                    rowC[sr] = corr;
                }
            }
            uint32_t* pw = Pbw + sr * PVLDW2 + sq * 8;
            #pragma unroll
            for (int j = 0; j < 8; j++) {
                float a = p[2*j], bq = p[2*j+1];
                float ha = __bfloat162float(__float2bfloat16(a));
                float hb = __bfloat162float(__float2bfloat16(bq));
                pw[j]      = pack_bf2(a, bq);
                pw[32 + j] = pack_bf2(a - ha, bq - hb);
            }
        }
        __syncthreads();

        // ---- rescale O, then P.V: logical K'=192 via kk-maps ----
        {
            float cf0 = rowC[r0l + g], cf1 = rowC[r0l + g + 8];
            #pragma unroll
            for (int nt = 0; nt < 8; nt++) {
                O[nt][0] *= cf0; O[nt][1] *= cf0;
                O[nt][2] *= cf1; O[nt][3] *= cf1;
            }
        }
        #pragma unroll
        for (int kk = 0; kk < 12; kk++) {
            const int kkA = (kk < 8) ? (kk & 3) : (kk - 4);    // P: [h|h|l]
            const int kkB = (kk < 8) ? kk : (kk - 8);          // V: [h|l|h]
            uint32_t af[4];
            ldsm4(af, aPaddr + kkA * 32);
            #pragma unroll
            for (int p = 0; p < 4; p++) {
                uint32_t bv[4];
                ldsm4(bv, bVaddr + p * (16 * PVLDW2 << 2) + kkB * 32);
                mma16816(O[p*2    ], af, &bv[0]);
                mma16816(O[p*2 + 1], af, &bv[2]);
            }
        }
    }

    __syncthreads();
    if (tid < 64) {
        float lsum = rowL[tid];
        rowC[tid] = 1.0f / lsum;
        g_lse[(size_t)bh * Ss + q0 + tid] = rowM[tid] + logf(lsum);
    }
    __syncthreads();
    {
        float invl0 = rowC[r0l + g], invl1 = rowC[r0l + g + 8];
        float* d0 = g_ctx + ((size_t)(b * Ss + q0 + r0l + g    )) * Dd + h * HDd;
        float* d1 = g_ctx + ((size_t)(b * Ss + q0 + r0l + g + 8)) * Dd + h * HDd;
        #pragma unroll
        for (int nt = 0; nt < 8; nt++) {
            int col = wo0 + nt * 8 + 2 * t;
            *(float2*)(d0 + col) = make_float2(O[nt][0] * invl0, O[nt][1] * invl0);
            *(float2*)(d1 + col) = make_float2(O[nt][2] * invl1, O[nt][3] * invl1);
        }
    }
}

// ---------------- avg_attn: stream spilled scores ----------------
__global__ __launch_bounds__(256)
void avg_kernel(float* __restrict__ avg)
{
    const int tid = threadIdx.x;
    const int b = blockIdx.z, qt = blockIdx.y, kt = blockIdx.x;
    const int q0 = qt * 64, k0 = kt * 64;
    const int r = tid >> 2, c0 = (tid & 3) * 16;
    float* drow = avg + ((size_t)(b * Ss + q0 + r)) * Ss + k0 + c0;

    if (kt > qt) {
        float4 z = make_float4(0.f, 0.f, 0.f, 0.f);
        #pragma unroll
        for (int i = 0; i < 4; i++) ((float4*)drow)[i] = z;
        return;
    }

    size_t tbase = ((size_t)b * NTRI + (size_t)(qt*(qt+1)/2 + kt)) * Hh * 4096;
    float acc[16];
    #pragma unroll
    for (int j = 0; j < 16; j++) acc[j] = 0.0f;

    for (int h = 0; h < Hh; h++) {
        float lse = g_lse[((size_t)(b * Hh + h)) * Ss + q0 + r];
        const float4* sp = (const float4*)(g_sc + tbase + (size_t)h * 4096 + r * 64 + c0);
        #pragma unroll
        for (int i = 0; i < 4; i++) {
            float4 s4 = sp[i];
            acc[4*i+0] += __expf(s4.x - lse);
            acc[4*i+1] += __expf(s4.y - lse);
            acc[4*i+2] += __expf(s4.z - lse);
            acc[4*i+3] += __expf(s4.w - lse);
        }
    }
    #pragma unroll
    for (int i = 0; i < 4; i++) {
        float4 v = make_float4(acc[4*i+0]*0.0625f, acc[4*i+1]*0.0625f,
                               acc[4*i+2]*0.0625f, acc[4*i+3]*0.0625f);
        ((float4*)drow)[i] = v;
    }
}

// ---------------- launch ----------------
extern "C" void kernel_launch(void* const* d_in, const int* in_sizes, int n_in,
                              void* d_out, int out_size)
{
    const float* x    = (const float*)d_in[0];
    const void*  kpm  = d_in[1];
    const float* inw  = (const float*)d_in[3];
    const float* inb  = (const float*)d_in[4];
    const float* outw = (const float*)d_in[5];
    const float* outb = (const float*)d_in[6];

    float* out = (float*)d_out;
    float* avg = out + OUT_ELEMS;

    cudaFuncSetAttribute(gemm_mma_kernel, cudaFuncAttributeMaxDynamicSharedMemorySize, GM_SMEM);
    cudaFuncSetAttribute(flash_kernel, cudaFuncAttributeMaxDynamicSharedMemorySize, FLASH_SMEM);
    cudaFuncSetAttribute(vsplit_kernel, cudaFuncAttributeMaxDynamicSharedMemorySize, VS_SMEM);

    mask_norm_kernel<<<1, 256>>>(kpm, BSr);

    {
        long long n4;
        n4 = (long long)BSr * Dd / 4;
        split_kernel<<<(unsigned)((n4 + 255) / 256), 256>>>(x, n4, 0);
        n4 = (long long)3 * Dd * Dd / 4;
        split_kernel<<<(unsigned)((n4 + 255) / 256), 256>>>(inw, n4, 1);
        n4 = (long long)Dd * Dd / 4;
        split_kernel<<<(unsigned)((n4 + 255) / 256), 256>>>(outw, n4, 2);
    }

    // QKV projection (q/k [h|l] + v fp32)
    gemm_mma_kernel<<<dim3(3*Dd/128, BSr/128), 256, GM_SMEM>>>(0, inb, nullptr, 3*Dd, 1);

    // one-shot V transpose+split ([h|l])
    vsplit_kernel<<<dim3(Ss/128, Bb*Hh), 256, VS_SMEM>>>();

    // flash attention
    flash_kernel<<<dim3(Ss/64, Bb*Hh), 256, FLASH_SMEM>>>();

    // ---- fork: avg (stream s2) || ctx-split + out-proj (stream 0) ----
    cudaStream_t s2;
    cudaStreamCreateWithFlags(&s2, cudaStreamNonBlocking);
    cudaEvent_t e1, e2;
    cudaEventCreateWithFlags(&e1, cudaEventDisableTiming);
    cudaEventCreateWithFlags(&e2, cudaEventDisableTiming);

    cudaEventRecord(e1, 0);
    cudaStreamWaitEvent(s2, e1, 0);
    avg_kernel<<<dim3(NT, NT, Bb), 256, 0, s2>>>(avg);
    cudaEventRecord(e2, s2);

    {
        long long n4 = (long long)BSr * Dd / 4;
        split_kernel<<<(unsigned)((n4 + 255) / 256), 256>>>(nullptr, n4, 3);
    }
    gemm_mma_kernel<<<dim3(Dd/128, BSr/128), 256, GM_SMEM>>>(1, outb, out, Dd, 0);

    cudaStreamWaitEvent(0, e2, 0);
    // s2/e1/e2 intentionally not destroyed (graph capture safety; replays don't re-run host code)
}